// round 6
// baseline (speedup 1.0000x reference)
#include <cuda_runtime.h>
#include <cuda_bf16.h>
#include <math.h>

#define B_   16
#define T_   500
#define D_   512
#define N_   128
#define E_   640
#define H_   1024
#define A_   1024
#define P_   1024
#define V_   10025
#define KIH  1152              // E_ + D_
#define KRO  2176              // H_ + E_ + D_
#define ZH_  0.05f

// ----------------------------- scratch ------------------------------------
__device__ float g_encctx[B_ * T_ * A_];          // enc @ W_enc_ctx^T + b
__device__ float g_invf[B_ * T_];                 // 0.5 * sigmoid(enc @ w_f)
__device__ float g_h_t[H_ * B_];                  // h transposed [k][b]
__device__ float g_ctx_t[D_ * B_];                // ctx transposed [d][b]
__device__ float g_accum[B_ * T_];
__device__ float g_energy[B_ * T_];
__device__ float g_st[B_ * A_];                   // s_t [b][a]
__device__ float g_gemb[B_ * N_ * 3 * H_];        // emb-part of gates + biases
__device__ float g_rin[B_ * N_ * KRO];            // [h | emb | ctx] rows
__device__ float g_ro[B_ * N_ * (P_ / 2)];        // post-maxout readout
__device__ float g_wih_e[3 * H_ * E_];            // packed i,g,o rows (emb cols)
__device__ float g_wct[D_ * 3 * H_];              // ctx-part, k-major [512][3072]
__device__ float g_ws_t[H_ * A_];                 // W_s^T  [k][a]
__device__ float g_b3[3 * H_];                    // b_ih + b_hh (i,g,o)
__device__ int   g_lab64;
__device__ unsigned g_barA;
__device__ unsigned g_barG;

// ----------------------------- helpers ------------------------------------
__device__ __forceinline__ float fsig(float x) {
    return __fdividef(1.0f, 1.0f + __expf(-x));
}
__device__ __forceinline__ float ftanh(float x) {      // accurate (cell)
    float a = fabsf(x);
    float e = __expf(-2.0f * a);
    float r = __fdividef(1.0f - e, 1.0f + e);
    return copysignf(r, x);
}
__device__ __forceinline__ float tanha(float x) {      // HW approx (energies)
    float y;
    asm("tanh.approx.f32 %0, %1;" : "=f"(y) : "f"(x));
    return y;
}
__device__ __forceinline__ unsigned long long packf2(float lo, float hi) {
    unsigned long long r;
    asm("mov.b64 %0, {%1, %2};" : "=l"(r) : "f"(lo), "f"(hi));
    return r;
}
#define FMA2(acc, a, b) \
    asm("fma.rn.f32x2 %0, %1, %2, %0;" : "+l"(acc) : "l"(a), "l"(b))
__device__ __forceinline__ void unpackf2(unsigned long long v, float& lo, float& hi) {
    asm("mov.b64 {%0, %1}, %2;" : "=f"(lo), "=f"(hi) : "l"(v));
}

// grid barrier: CG-style arrive(release) + spin(acquire) by thread 0 only
__device__ __forceinline__ void gridbar(int nb) {
    __syncthreads();
    if (threadIdx.x == 0) {
        unsigned gen, ticket;
        asm volatile("ld.acquire.gpu.u32 %0, [%1];"
                     : "=r"(gen) : "l"(&g_barG) : "memory");
        asm volatile("atom.release.gpu.add.u32 %0, [%1], 1;"
                     : "=r"(ticket) : "l"(&g_barA) : "memory");
        if (ticket == (unsigned)(nb - 1)) {
            asm volatile("st.relaxed.gpu.u32 [%0], 0;" :: "l"(&g_barA) : "memory");
            unsigned d;
            asm volatile("atom.release.gpu.add.u32 %0, [%1], 1;"
                         : "=r"(d) : "l"(&g_barG) : "memory");
        } else {
            unsigned cur;
            do {
                __nanosleep(32);
                asm volatile("ld.acquire.gpu.u32 %0, [%1];"
                             : "=r"(cur) : "l"(&g_barG) : "memory");
            } while (cur == gen);
        }
    }
    __syncthreads();
}

// ------------------------ labels dtype detection ---------------------------
__global__ void k_detect(const int* __restrict__ lab32) {
    int ok = 1;
    for (int i = threadIdx.x; i < 1024; i += blockDim.x)
        if (lab32[2 * i + 1] != 0) ok = 0;
    int all = __syncthreads_and(ok);
    if (threadIdx.x == 0) g_lab64 = all;
}

// ------------------ shifted embedding gather into g_rin --------------------
__global__ void k_gather(const void* __restrict__ labels,
                         const float* __restrict__ embed) {
    int row = blockIdx.x;                  // b*N_ + n
    int n = row & (N_ - 1);
    int b = row >> 7;
    float4* dst = (float4*)(g_rin + (size_t)row * KRO + H_);
    if (n == 0) {
        for (int k = threadIdx.x; k < E_ / 4; k += blockDim.x)
            dst[k] = make_float4(0.f, 0.f, 0.f, 0.f);
        return;
    }
    int idx = b * N_ + n - 1;
    int lab = g_lab64 ? (int)((const long long*)labels)[idx]
                      : ((const int*)labels)[idx];
    if (lab < 0) lab = 0;
    if (lab >= V_) lab = V_ - 1;
    const float4* src = (const float4*)(embed + (size_t)lab * E_);
    for (int k = threadIdx.x; k < E_ / 4; k += blockDim.x) dst[k] = src[k];
}

// ------------- pack emb-part of W_ih rows (drop f) + fold biases -----------
__global__ void k_pack(const float* __restrict__ W_ih,
                       const float* __restrict__ b_ih,
                       const float* __restrict__ b_hh) {
    int jj = blockIdx.x;                         // 0..3071 (i,g,o)
    int src = (jj < 1024) ? jj : jj + 1024;      // skip f rows [1024,2048)
    const float* s = W_ih + (size_t)src * KIH;
    for (int k = threadIdx.x; k < E_; k += 256)
        g_wih_e[(size_t)jj * E_ + k] = s[k];
    if (threadIdx.x == 0) g_b3[jj] = b_ih[src] + b_hh[src];
}

// ---------- transpose ctx-part of W_ih into g_wct [512][3072] --------------
__global__ void k_twct(const float* __restrict__ W_ih) {
    __shared__ float tl[32][33];
    int gc0 = blockIdx.x * 32, k0 = blockIdx.y * 32;
    int tx = threadIdx.x, ty = threadIdx.y;
    for (int i = ty; i < 32; i += 8) {
        int gc = gc0 + i;
        int src = (gc < 1024) ? gc : gc + 1024;
        tl[i][tx] = W_ih[(size_t)src * KIH + E_ + k0 + tx];
    }
    __syncthreads();
    for (int i = ty; i < 32; i += 8)
        g_wct[(size_t)(k0 + i) * (3 * H_) + gc0 + tx] = tl[tx][i];
}

// ---------------- transpose W_s into g_ws_t [k][a] -------------------------
__global__ void k_tws(const float* __restrict__ W_s) {
    __shared__ float tl[32][33];
    int j0 = blockIdx.x * 32, k0 = blockIdx.y * 32;
    int tx = threadIdx.x, ty = threadIdx.y;
    for (int i = ty; i < 32; i += 8)
        tl[i][tx] = W_s[(size_t)(j0 + i) * H_ + k0 + tx];
    __syncthreads();
    for (int i = ty; i < 32; i += 8)
        g_ws_t[(size_t)(k0 + i) * A_ + j0 + tx] = tl[tx][i];
}

// ----------------------- inverse fertility ---------------------------------
__global__ void __launch_bounds__(256) k_invf(const float* __restrict__ enc,
                                              const float* __restrict__ wf) {
    __shared__ float wsh[D_];
    int tid = threadIdx.x;
    for (int i = tid; i < D_; i += 256) wsh[i] = wf[i];
    __syncthreads();
    int row  = blockIdx.x * 8 + (tid >> 5);
    int lane = tid & 31;
    if (row >= B_ * T_) return;
    const float4* ep = (const float4*)(enc + (size_t)row * D_);
    const float4* wp = (const float4*)wsh;
    float acc = 0.0f;
#pragma unroll
    for (int i = 0; i < 4; i++) {
        float4 e = ep[i * 32 + lane];
        float4 w = wp[i * 32 + lane];
        acc = fmaf(e.x, w.x, fmaf(e.y, w.y, fmaf(e.z, w.z, fmaf(e.w, w.w, acc))));
    }
#pragma unroll
    for (int o = 16; o; o >>= 1) acc += __shfl_down_sync(0xffffffffu, acc, o);
    if (lane == 0) g_invf[row] = 0.5f * fsig(acc);
}

// ---------- fp32 SGEMM C = A·B^T + bias, f32x2 inner (2x FP32) -------------
// mode 0: plain; mode 1: fused MaxOut(2) (ldc = N/2)
__global__ void __launch_bounds__(256) k_sgemm(const float* __restrict__ A,
                                               int lda,
                                               const float* __restrict__ Bm,
                                               const float* __restrict__ bias,
                                               float* __restrict__ C,
                                               int M, int N, int K, int ldc,
                                               int mode) {
    __shared__ float As[8][128];
    __shared__ float Bs[8][128];
    int tid = threadIdx.x;
    int row0 = blockIdx.y * 128, col0 = blockIdx.x * 128;
    int tx = tid & 15, ty = tid >> 4;
    unsigned long long acc2[8][4];
#pragma unroll
    for (int i = 0; i < 8; i++)
#pragma unroll
        for (int p = 0; p < 4; p++) acc2[i][p] = 0ULL;
    int lr = tid >> 1;
    int lq = (tid & 1) * 4;
    const float* Ap = A  + (size_t)(row0 + lr) * lda + lq;
    const float* Bp = Bm + (size_t)(col0 + lr) * K + lq;
    bool avalid = (row0 + lr) < M;
    bool bvalid = (col0 + lr) < N;
    for (int k0 = 0; k0 < K; k0 += 8) {
        float4 av = avalid ? *(const float4*)(Ap + k0) : make_float4(0, 0, 0, 0);
        float4 bv = bvalid ? *(const float4*)(Bp + k0) : make_float4(0, 0, 0, 0);
        As[lq + 0][lr] = av.x; As[lq + 1][lr] = av.y;
        As[lq + 2][lr] = av.z; As[lq + 3][lr] = av.w;
        Bs[lq + 0][lr] = bv.x; Bs[lq + 1][lr] = bv.y;
        Bs[lq + 2][lr] = bv.z; Bs[lq + 3][lr] = bv.w;
        __syncthreads();
#pragma unroll
        for (int k = 0; k < 8; k++) {
            float ar[8], br[8];
            *(float4*)(ar)     = *(const float4*)&As[k][ty * 8];
            *(float4*)(ar + 4) = *(const float4*)&As[k][ty * 8 + 4];
            *(float4*)(br)     = *(const float4*)&Bs[k][tx * 8];
            *(float4*)(br + 4) = *(const float4*)&Bs[k][tx * 8 + 4];
            unsigned long long brp[4];
#pragma unroll
            for (int p = 0; p < 4; p++) brp[p] = packf2(br[2 * p], br[2 * p + 1]);
#pragma unroll
            for (int i = 0; i < 8; i++) {
                unsigned long long aa = packf2(ar[i], ar[i]);
#pragma unroll
                for (int p = 0; p < 4; p++) FMA2(acc2[i][p], aa, brp[p]);
            }
        }
        __syncthreads();
    }
    float acc[8][8];
#pragma unroll
    for (int i = 0; i < 8; i++)
#pragma unroll
        for (int p = 0; p < 4; p++)
            unpackf2(acc2[i][p], acc[i][2 * p], acc[i][2 * p + 1]);
    if (mode == 0) {
#pragma unroll
        for (int i = 0; i < 8; i++) {
            int m = row0 + ty * 8 + i;
            if (m >= M) break;
#pragma unroll
            for (int j = 0; j < 8; j++) {
                int nn = col0 + tx * 8 + j;
                if (nn < N) C[(size_t)m * ldc + nn] = acc[i][j] + bias[nn];
            }
        }
    } else {
#pragma unroll
        for (int i = 0; i < 8; i++) {
            int m = row0 + ty * 8 + i;
            if (m >= M) break;
#pragma unroll
            for (int p = 0; p < 4; p++) {
                int nn = col0 + tx * 8 + p * 2;
                float v0 = acc[i][2 * p]     + bias[nn];
                float v1 = acc[i][2 * p + 1] + bias[nn + 1];
                C[(size_t)m * ldc + (nn >> 1)] = fmaxf(v0, v1);
            }
        }
    }
}

// ================= persistent recurrence kernel (all 128 steps) ============
__global__ void __launch_bounds__(256, 3) k_loop(const float* __restrict__ enc,
                                                 const int* __restrict__ seqlen,
                                                 const float* __restrict__ v_att,
                                                 const float* __restrict__ W_fb) {
    __shared__ float sm_v[A_], sm_f[A_];
    __shared__ float sm_red[256];
    __shared__ float sw[512];
    int tid = threadIdx.x;
    int bk  = blockIdx.x;
    int nb  = gridDim.x;
    int gw  = bk * 256 + tid;

    for (int i = tid; i < A_; i += 256) { sm_v[i] = v_att[i]; sm_f[i] = W_fb[i]; }
    for (int i = gw; i < H_ * B_; i += nb * 256) g_h_t[i]   = 0.0f;
    for (int i = gw; i < D_ * B_; i += nb * 256) g_ctx_t[i] = 0.0f;
    for (int i = gw; i < B_ * T_; i += nb * 256) g_accum[i] = 0.0f;
    gridbar(nb);

    for (int n = 0; n < N_; n++) {
        // ===== phase A: gates(ctx part) + activation -> h ==================
        // 256 units x 4 j; thread = (gate 0..2, bg 0..3, ks 0..15), k-range 32
        for (int u = bk; u < 256; u += nb) {
            if (tid < 192) {
                int gate = tid / 64;
                int r = tid % 64;
                int bg = r >> 4, ks = r & 15;
                float acc[16];
#pragma unroll
                for (int q = 0; q < 16; q++) acc[q] = 0.0f;
                const float4* wp = (const float4*)g_wct;
                const float4* cp = (const float4*)g_ctx_t;
                int wbase = gate * 256 + u;
#pragma unroll 4
                for (int i = 0; i < 32; i++) {
                    int k = ks * 32 + i;
                    float4 w = wp[k * 768 + wbase];
                    float4 c = cp[k * 4 + bg];
                    acc[0]  = fmaf(w.x, c.x, acc[0]);  acc[1]  = fmaf(w.x, c.y, acc[1]);
                    acc[2]  = fmaf(w.x, c.z, acc[2]);  acc[3]  = fmaf(w.x, c.w, acc[3]);
                    acc[4]  = fmaf(w.y, c.x, acc[4]);  acc[5]  = fmaf(w.y, c.y, acc[5]);
                    acc[6]  = fmaf(w.y, c.z, acc[6]);  acc[7]  = fmaf(w.y, c.w, acc[7]);
                    acc[8]  = fmaf(w.z, c.x, acc[8]);  acc[9]  = fmaf(w.z, c.y, acc[9]);
                    acc[10] = fmaf(w.z, c.z, acc[10]); acc[11] = fmaf(w.z, c.w, acc[11]);
                    acc[12] = fmaf(w.w, c.x, acc[12]); acc[13] = fmaf(w.w, c.y, acc[13]);
                    acc[14] = fmaf(w.w, c.z, acc[14]); acc[15] = fmaf(w.w, c.w, acc[15]);
                }
#pragma unroll
                for (int m = 8; m; m >>= 1)
#pragma unroll
                    for (int q = 0; q < 16; q++)
                        acc[q] += __shfl_xor_sync(0xffffffffu, acc[q], m);
                if (ks == 0) {
#pragma unroll
                    for (int q = 0; q < 16; q++)
                        sm_red[(gate * 4 + bg) * 16 + q] = acc[q];
                }
            }
            __syncthreads();
            if (tid < 64) {
                int jl = tid >> 4, b = tid & 15;
                int bg = b >> 2, bl = b & 3;
                float gi = sm_red[(0 + bg) * 16 + jl * 4 + bl];
                float gg = sm_red[(4 + bg) * 16 + jl * 4 + bl];
                float go = sm_red[(8 + bg) * 16 + jl * 4 + bl];
                int j = u * 4 + jl;
                size_t row = (size_t)(b * N_ + n) * (3 * H_);
                gi += g_gemb[row + j];
                gg += g_gemb[row + H_ + j];
                go += g_gemb[row + 2 * H_ + j];
                float c_new = fsig(gi) * ftanh(gg);
                float h_new = fsig(go) * ftanh(c_new);
                float h = ZH_ * g_h_t[j * 16 + b] + (1.0f - ZH_) * h_new;
                g_h_t[j * 16 + b] = h;
                g_rin[(size_t)(b * N_ + n) * KRO + j] = h;
            }
            __syncthreads();
        }
        gridbar(nb);

        // ===== phase B: s_t = h @ W_s^T =====================================
        // 256 units x 4 a; thread = (bg 0..3, ks 0..63), k-range 16
        for (int u = bk; u < 256; u += nb) {
            int bg = tid >> 6, ks = tid & 63;
            float acc[16];
#pragma unroll
            for (int q = 0; q < 16; q++) acc[q] = 0.0f;
            const float4* wp = (const float4*)g_ws_t;
            const float4* hp = (const float4*)g_h_t;
#pragma unroll 4
            for (int i = 0; i < 16; i++) {
                int k = ks * 16 + i;
                float4 w = wp[k * 256 + u];
                float4 h = hp[k * 4 + bg];
                acc[0]  = fmaf(w.x, h.x, acc[0]);  acc[1]  = fmaf(w.x, h.y, acc[1]);
                acc[2]  = fmaf(w.x, h.z, acc[2]);  acc[3]  = fmaf(w.x, h.w, acc[3]);
                acc[4]  = fmaf(w.y, h.x, acc[4]);  acc[5]  = fmaf(w.y, h.y, acc[5]);
                acc[6]  = fmaf(w.y, h.z, acc[6]);  acc[7]  = fmaf(w.y, h.w, acc[7]);
                acc[8]  = fmaf(w.z, h.x, acc[8]);  acc[9]  = fmaf(w.z, h.y, acc[9]);
                acc[10] = fmaf(w.z, h.z, acc[10]); acc[11] = fmaf(w.z, h.w, acc[11]);
                acc[12] = fmaf(w.w, h.x, acc[12]); acc[13] = fmaf(w.w, h.y, acc[13]);
                acc[14] = fmaf(w.w, h.z, acc[14]); acc[15] = fmaf(w.w, h.w, acc[15]);
            }
#pragma unroll
            for (int m = 16; m; m >>= 1)
#pragma unroll
                for (int q = 0; q < 16; q++)
                    acc[q] += __shfl_xor_sync(0xffffffffu, acc[q], m);
            if ((tid & 31) == 0) {
                int wrp = tid >> 5;
#pragma unroll
                for (int q = 0; q < 16; q++)
                    sm_red[wrp * 16 + q] = acc[q];
            }
            __syncthreads();
            if (tid < 64) {
                int al = tid >> 4, b = tid & 15;
                int bg2 = b >> 2, bl = b & 3;
                float s = sm_red[(bg2 * 2 + 0) * 16 + al * 4 + bl]
                        + sm_red[(bg2 * 2 + 1) * 16 + al * 4 + bl];
                g_st[b * A_ + u * 4 + al] = s;
            }
            __syncthreads();
        }
        gridbar(nb);

        // ===== phase C: attention energies (seqlen-clipped) ================
        // 1024 units = (b, 8-t chunk); one warp per t
        for (int u = bk; u < 1024; u += nb) {
            int b = u >> 6, tc = u & 63;
            int w = tid >> 5, lane = tid & 31;
            int t = tc * 8 + w;
            if (t < T_) {
                int Tb = seqlen[b];
                if (t >= Tb) {
                    if (lane == 0) g_energy[b * T_ + t] = -1e30f;
                } else {
                    float a = g_accum[b * T_ + t];
                    const float4* ec = (const float4*)g_encctx
                                     + (size_t)(b * T_ + t) * 256;
                    const float4* s4 = (const float4*)(g_st + b * A_);
                    const float4* v4 = (const float4*)sm_v;
                    const float4* f4 = (const float4*)sm_f;
                    float acc = 0.f;
#pragma unroll
                    for (int kk = 0; kk < 8; kk++) {
                        float4 e = ec[kk * 32 + lane];
                        float4 sv = s4[kk * 32 + lane];
                        float4 fv = f4[kk * 32 + lane];
                        float4 vv = v4[kk * 32 + lane];
                        acc += vv.x * tanha(e.x + sv.x + a * fv.x);
                        acc += vv.y * tanha(e.y + sv.y + a * fv.y);
                        acc += vv.z * tanha(e.z + sv.z + a * fv.z);
                        acc += vv.w * tanha(e.w + sv.w + a * fv.w);
                    }
#pragma unroll
                    for (int o = 16; o; o >>= 1)
                        acc += __shfl_down_sync(0xffffffffu, acc, o);
                    if (lane == 0) g_energy[b * T_ + t] = acc;
                }
            }
        }
        gridbar(nb);

        // ===== phase D: softmax + context + fertility accum ================
        // 512 units = (b, 16-d chunk)
        for (int u = bk; u < 512; u += nb) {
            int b = u >> 5, ch = u & 31, d0 = ch * 16;
            int Tb = seqlen[b];
            float m = -1e30f;
            for (int t = tid; t < Tb; t += 256)
                m = fmaxf(m, g_energy[b * T_ + t]);
            sm_red[tid] = m; __syncthreads();
            for (int o = 128; o; o >>= 1) {
                if (tid < o) sm_red[tid] = fmaxf(sm_red[tid], sm_red[tid + o]);
                __syncthreads();
            }
            float mx = sm_red[0]; __syncthreads();
            float s = 0.f;
            for (int t = tid; t < Tb; t += 256) {
                float e = __expf(g_energy[b * T_ + t] - mx);
                sw[t] = e;
                s += e;
            }
            sm_red[tid] = s; __syncthreads();
            for (int o = 128; o; o >>= 1) {
                if (tid < o) sm_red[tid] += sm_red[tid + o];
                __syncthreads();
            }
            float inv = __fdividef(1.0f, sm_red[0]); __syncthreads();
            for (int t = tid; t < Tb; t += 256) sw[t] *= inv;
            __syncthreads();
            int dl = tid & 15, ts = tid >> 4;
            float acc = 0.f;
            for (int t = ts; t < Tb; t += 16)
                acc = fmaf(sw[t], enc[(size_t)(b * T_ + t) * D_ + d0 + dl], acc);
            sm_red[ts * 16 + dl] = acc; __syncthreads();
            if (tid < 16) {
                float v = 0.f;
#pragma unroll
                for (int q = 0; q < 16; q++) v += sm_red[q * 16 + tid];
                int dd = d0 + tid;
                g_ctx_t[dd * 16 + b] = v;
                g_rin[(size_t)(b * N_ + n) * KRO + H_ + E_ + dd] = v;
            }
            if (ch == 0)
                for (int t = tid; t < Tb; t += 256)
                    g_accum[b * T_ + t] += sw[t] * g_invf[b * T_ + t];
            __syncthreads();
        }
        gridbar(nb);
    }
}

// ----------------------------- launch --------------------------------------
extern "C" void kernel_launch(void* const* d_in, const int* in_sizes, int n_in,
                              void* d_out, int out_size) {
    const float* enc     = (const float*)d_in[0];
    const void*  labels  =               d_in[1];
    const int*   seqlen  = (const int*)  d_in[2];
    const float* embed   = (const float*)d_in[3];
    const float* W_ih    = (const float*)d_in[4];
    const float* b_ih    = (const float*)d_in[5];
    const float* b_hh    = (const float*)d_in[6];
    const float* W_s     = (const float*)d_in[7];
    const float* W_encc  = (const float*)d_in[8];
    const float* b_encc  = (const float*)d_in[9];
    const float* v_att   = (const float*)d_in[10];
    const float* W_invf  = (const float*)d_in[11];
    const float* W_fb    = (const float*)d_in[12];
    const float* W_ro    = (const float*)d_in[13];
    const float* b_ro    = (const float*)d_in[14];
    const float* W_out   = (const float*)d_in[15];
    const float* b_out   = (const float*)d_in[16];
    float* out = (float*)d_out;

    float* encctx; cudaGetSymbolAddress((void**)&encctx, g_encctx);
    float* rin;    cudaGetSymbolAddress((void**)&rin,    g_rin);
    float* ro;     cudaGetSymbolAddress((void**)&ro,     g_ro);
    float* wihe;   cudaGetSymbolAddress((void**)&wihe,   g_wih_e);
    float* gemb;   cudaGetSymbolAddress((void**)&gemb,   g_gemb);
    float* b3;     cudaGetSymbolAddress((void**)&b3,     g_b3);

    // co-residency-guaranteed persistent grid
    int occ = 0, sms = 0;
    cudaOccupancyMaxActiveBlocksPerMultiprocessor(&occ, k_loop, 256, 0);
    cudaDeviceGetAttribute(&sms, cudaDevAttrMultiProcessorCount, 0);
    if (occ < 1) occ = 1;
    if (sms < 1) sms = 148;
    int nb = occ * sms;

    k_detect<<<1, 256>>>((const int*)labels);
    k_gather<<<B_ * N_, 160>>>(labels, embed);
    k_pack<<<3 * H_, 256>>>(W_ih, b_ih, b_hh);
    { dim3 blk(32, 8); k_twct<<<dim3(96, 16), blk>>>(W_ih); }
    { dim3 blk(32, 8); k_tws <<<dim3(32, 32), blk>>>(W_s);  }
    k_invf<<<(B_ * T_ + 7) / 8, 256>>>(enc, W_invf);

    // enc_ctx = enc @ W_enc_ctx^T + b   [8000 x 1024]
    k_sgemm<<<dim3(A_ / 128, (B_ * T_ + 127) / 128), 256>>>(
        enc, D_, W_encc, b_encc, encctx, B_ * T_, A_, D_, A_, 0);
    // gemb = emb @ W_e^T + (b_ih+b_hh)  [2048 x 3072]
    k_sgemm<<<dim3(3 * H_ / 128, (B_ * N_) / 128), 256>>>(
        rin + H_, KRO, wihe, b3, gemb, B_ * N_, 3 * H_, E_, 3 * H_, 0);

    // entire 128-step recurrence in one persistent kernel
    k_loop<<<nb, 256>>>(enc, seqlen, v_att, W_fb);

    // readout (+MaxOut) then vocab projection
    k_sgemm<<<dim3(P_ / 128, (B_ * N_) / 128), 256>>>(
        rin, KRO, W_ro, b_ro, ro, B_ * N_, P_, KRO, P_ / 2, 1);
    k_sgemm<<<dim3((V_ + 127) / 128, (B_ * N_) / 128), 256>>>(
        ro, P_ / 2, W_out, b_out, out, B_ * N_, V_, P_ / 2, V_, 0);
}